// round 11
// baseline (speedup 1.0000x reference)
#include <cuda_runtime.h>
#include <math.h>

// ---------------- scratch (device globals: allocation-free rule) ----------------
__device__ float g_h1[32u * 64 * 128 * 128];   // after conv1+relu   (NCHW, tf32-rounded)
__device__ float g_h2[32u * 128 * 64 * 64];    // after conv2+relu   (NCHW, tf32-rounded)
__device__ float g_z [32u * 64 * 64 * 64];     // after conv3+relu   (NCHW, fp32)
__device__ float g_q [32u * 64 * 64 * 64];     // quantized          (NCHW, tf32-rounded)
__device__ float g_d1[32u * 128 * 128 * 128];  // after deconv1+relu (NCHW, tf32-rounded)
__device__ float g_d2[32u * 64 * 256 * 256];   // after deconv2+relu (NCHW, fp32)

// repacked weights
__device__ float  g_wt1 [64 * 3 * 16];          // c1 scalar path
__device__ float  g_wt3d[3 * 64 * 9];           // dc3 flipped -> plain conv
__device__ float2 g_pw1f[4 * 32 * 16 * 32];     // dc1 B [p][s][ntf][lane]
__device__ float2 g_pw2f[4 * 64 * 8 * 32];      // dc2 B
__device__ float2 g_cw2f[128 * 16 * 32];        // c2  B [s][ntf][lane]
__device__ float2 g_cw3f[64 * 3 * 8 * 32];      // c3  B (12 taps, kw=3 zeroed)

__device__ float g_loss;

// ---------------- helpers ----------------
__device__ __forceinline__ float cvt_tf32(float x) {
    asm("cvt.rna.tf32.f32 %0, %0;" : "+f"(x));
    return x;
}
__device__ __forceinline__ unsigned long long pk2(float x) {
    unsigned long long r;
    asm("mov.b64 %0, {%1, %1};" : "=l"(r) : "f"(x));
    return r;
}
__device__ __forceinline__ unsigned long long pk(float x, float y) {
    unsigned long long r;
    asm("mov.b64 %0, {%1, %2};" : "=l"(r) : "f"(x), "f"(y));
    return r;
}
__device__ __forceinline__ void fma2(unsigned long long& d,
                                     unsigned long long a, unsigned long long b) {
    asm("fma.rn.f32x2 %0, %1, %2, %0;" : "+l"(d) : "l"(a), "l"(b));
}
__device__ __forceinline__ float2 up2(unsigned long long v) {
    float2 f;
    asm("mov.b64 {%0, %1}, %2;" : "=f"(f.x), "=f"(f.y) : "l"(v));
    return f;
}
__device__ __forceinline__ void mma_tf32(float* c, unsigned a0, unsigned a1,
                                         unsigned a2, unsigned a3,
                                         unsigned b0, unsigned b1) {
    asm volatile(
        "mma.sync.aligned.m16n8k8.row.col.f32.tf32.tf32.f32 "
        "{%0,%1,%2,%3}, {%4,%5,%6,%7}, {%8,%9}, {%0,%1,%2,%3};"
        : "+f"(c[0]), "+f"(c[1]), "+f"(c[2]), "+f"(c[3])
        : "r"(a0), "r"(a1), "r"(a2), "r"(a3), "r"(b0), "r"(b1));
}
__device__ __forceinline__ unsigned smem_u32(const void* p) {
    return (unsigned)__cvta_generic_to_shared(p);
}
__device__ __forceinline__ void cp_async4(unsigned dst, const void* src, bool pred) {
    int sz = pred ? 4 : 0;
    asm volatile("cp.async.ca.shared.global [%0], [%1], 4, %2;"
                 :: "r"(dst), "l"(src), "r"(sz));
}
__device__ __forceinline__ void cp_async16(unsigned dst, const void* src) {
    asm volatile("cp.async.cg.shared.global [%0], [%1], 16;" :: "r"(dst), "l"(src));
}
__device__ __forceinline__ void cp_commit() {
    asm volatile("cp.async.commit_group;");
}
template<int N> __device__ __forceinline__ void cp_wait() {
    asm volatile("cp.async.wait_group %0;" :: "n"(N));
}

// ---------------- fused weight repack (single launch; also zeroes loss) ----------------
__global__ void repack_all_k(const float* __restrict__ w1, const float* __restrict__ w2,
                             const float* __restrict__ w3, const float* __restrict__ dw1,
                             const float* __restrict__ dw2, const float* __restrict__ dw3,
                             float* __restrict__ wt1, float2* __restrict__ cw2f,
                             float2* __restrict__ cw3f, float2* __restrict__ pw1f,
                             float2* __restrict__ pw2f, float* __restrict__ wt3d) {
    int i = blockIdx.x * blockDim.x + threadIdx.x;
    if (i == 0) g_loss = 0.0f;

    if (i < 3072) {                       // c1 [(ci*16+t)*64+co]
        int co = i / 48, r = i % 48;
        wt1[r * 64 + co] = w1[i];
        return;
    }
    i -= 3072;
    if (i < 65536) {                      // c2 B frag order, NTF=16
        int lane = i & 31;
        int t1 = i >> 5;
        int nt = t1 % 16;
        int s  = t1 / 16;
        int ci = s >> 1, th = s & 1;
        int kw = lane & 3;
        int co = nt * 8 + (lane >> 2);
        float v0 = w2[((co * 64 + ci) * 4 + 2 * th) * 4 + kw];
        float v1 = w2[((co * 64 + ci) * 4 + 2 * th + 1) * 4 + kw];
        cw2f[i] = make_float2(cvt_tf32(v0), cvt_tf32(v1));
        return;
    }
    i -= 65536;
    if (i < 49152) {                      // c3 B frag order, NTF=8
        int lane = i & 31;
        int t1 = i >> 5;
        int nt = t1 % 8;
        int t2 = t1 / 8;
        int g  = t2 % 3;
        int s  = t2 / 3;
        int kw = lane & 3;
        int co = nt * 8 + (lane >> 2);
        float v0 = 0.0f, v1 = 0.0f;
        if (kw < 3) {
            v0 = w3[((co * 128 + 2 * s) * 3 + g) * 3 + kw];
            v1 = w3[((co * 128 + 2 * s + 1) * 3 + g) * 3 + kw];
        }
        cw3f[i] = make_float2(cvt_tf32(v0), cvt_tf32(v1));
        return;
    }
    i -= 49152;
    if (i < 65536) {                      // dc1 B parity-frag order, NTF=16
        int lane = i & 31;
        int t1 = i >> 5;
        int nt = t1 % 16;
        int t2 = t1 / 16;
        int s  = t2 % 32;
        int p  = t2 / 32;
        int tap = lane & 3;
        int a = tap >> 1, bt = tap & 1;
        int ph = p >> 1, pwb = p & 1;
        int kh = ph ? (a ? 0 : 2) : (a ? 3 : 1);
        int kw = pwb ? (bt ? 0 : 2) : (bt ? 3 : 1);
        int co = nt * 8 + (lane >> 2);
        float v0 = dw1[(((2 * s) * 128 + co) * 4 + kh) * 4 + kw];
        float v1 = dw1[(((2 * s + 1) * 128 + co) * 4 + kh) * 4 + kw];
        pw1f[i] = make_float2(cvt_tf32(v0), cvt_tf32(v1));
        return;
    }
    i -= 65536;
    if (i < 32768) {                      // dc2 B parity-frag order, NTF=8
        int lane = i & 31;
        int t1 = i >> 5;
        int nt = t1 % 8;
        int t2 = t1 / 8;
        int s  = t2 % 64;
        int p  = t2 / 64;
        int tap = lane & 3;
        int a = tap >> 1, bt = tap & 1;
        int ph = p >> 1, pwb = p & 1;
        int kh = ph ? (a ? 0 : 2) : (a ? 3 : 1);
        int kw = pwb ? (bt ? 0 : 2) : (bt ? 3 : 1);
        int co = nt * 8 + (lane >> 2);
        float v0 = dw2[(((2 * s) * 64 + co) * 4 + kh) * 4 + kw];
        float v1 = dw2[(((2 * s + 1) * 64 + co) * 4 + kh) * 4 + kw];
        pw2f[i] = make_float2(cvt_tf32(v0), cvt_tf32(v1));
        return;
    }
    i -= 32768;
    if (i < 1728) {                       // dc3 flip -> plain conv
        int ci = i / 27;
        int r  = i % 27;
        int co = r / 9;
        int t  = r % 9;
        int kh = t / 3, kw = t % 3;
        int tf = (2 - kh) * 3 + (2 - kw);
        wt3d[(ci * 9 + tf) * 3 + co] = dw3[i];
    }
}

__global__ void finalize_k(float* __restrict__ out, int loss_idx) {
    out[loss_idx] = 1.25f * g_loss * (1.0f / 8388608.0f);
}

// ================= MMA stride-2 deconv, M=32/warp, NT=4 via CO split =================
// blockIdx.x = parity + co-half (wave-adjacent -> shared input stays L2-hot).
template<int CI, int CO, int COSPLIT, int MH, int MW, int MWP, int HIN, int WIN,
         int KC, bool RND>
__global__ void __launch_bounds__(256, 3)
deconv_mma_k(const float* __restrict__ in, const float2* __restrict__ wf,
             const float* __restrict__ bias, float* __restrict__ out) {
    constexpr int R = MH + 1;
    constexpr int NTF = CO / 8;
    constexpr int NT = NTF / COSPLIT;
    constexpr int PLANE = R * MWP;
    constexpr int ASZ = KC * PLANE;
    constexpr int BSZ = (KC / 2) * NT * 32;       // float2 per buffer
    constexpr int SCHUNK = NT * 16;               // float4 units per s
    constexpr int NC = CI / KC;
    constexpr int HOUT = 2 * HIN, WOUT = 2 * WIN;
    extern __shared__ float sm[];
    float*  sA = sm;
    float2* sB = (float2*)(sm + 2 * ASZ);

    const int bx = blockIdx.x;
    const int p = bx & 3, coh = bx >> 2;
    const int ph = p >> 1, pw = p & 1;
    const int tiles_h = HIN / MH;
    const int h0 = (blockIdx.y % tiles_h) * MH;
    const int b  = blockIdx.y / tiles_h;
    const int warp = threadIdx.x >> 5, lane = threadIdx.x & 31;
    const int tap = lane & 3;
    const int a = tap >> 1, bt = tap & 1;
    const int roff = ph ? a : 1 - a;
    const int coff = pw ? bt : 1 - bt;
    const int mbase = warp * 32;                  // M=32 per warp
    const int mr = mbase / MW;
    const int colq = (mbase % MW) + 2 * (lane >> 2);
    const int aoff0 = (mr + roff) * MWP + colq + coff;

    float acc[NT][8];
#pragma unroll
    for (int nt = 0; nt < NT; nt++) {
        float b0v = bias[(coh * NT + nt) * 8 + 2 * (lane & 3)];
        float b1v = bias[(coh * NT + nt) * 8 + 2 * (lane & 3) + 1];
#pragma unroll
        for (int t = 0; t < 2; t++) {
            acc[nt][4 * t + 0] = b0v; acc[nt][4 * t + 1] = b1v;
            acc[nt][4 * t + 2] = b0v; acc[nt][4 * t + 3] = b1v;
        }
    }

    const float* inb = in + (size_t)b * CI * HIN * WIN;
    const char*  wpB = (const char*)wf
        + ((size_t)p * (CI / 2) * NTF * 32 + (size_t)coh * NT * 32) * 8;
    const unsigned sAu = smem_u32(sA);
    const unsigned sBu = smem_u32(sB);

    auto stageA = [&](int ci0, int buf) {
        for (int i = threadIdx.x; i < ASZ; i += 256) {
            int ci_l = i / PLANE;
            int rem  = i % PLANE;
            int r = rem / MWP, c = rem % MWP;
            int gr = h0 + r - (ph ? 0 : 1);
            int gc = c - (pw ? 0 : 1);
            bool ok = (unsigned)gr < (unsigned)HIN && (unsigned)gc < (unsigned)WIN;
            const float* src = inb + (size_t)(ci0 + ci_l) * HIN * WIN
                               + (ok ? gr * WIN + gc : 0);
            cp_async4(sAu + (buf * ASZ + i) * 4, src, ok);
        }
    };
    auto stageB = [&](int ci0, int buf) {
        for (int i = threadIdx.x; i < BSZ / 2; i += 256) {
            int s_k = i / SCHUNK, r = i % SCHUNK;
            const char* src = wpB + ((size_t)(ci0 / 2 + s_k) * NTF * 32) * 8 + r * 16;
            cp_async16(sBu + buf * BSZ * 8 + i * 16, src);
        }
    };

    stageA(0, 0); stageB(0, 0); cp_commit();
    for (int c = 0; c < NC; c++) {
        int buf = c & 1;
        if (c + 1 < NC) {
            stageA((c + 1) * KC, buf ^ 1);
            stageB((c + 1) * KC, buf ^ 1);
            cp_commit();
            cp_wait<1>();
        } else {
            cp_wait<0>();
        }
        __syncthreads();
        const float*  bA = sA + buf * ASZ;
        const float2* bB = sB + buf * BSZ;
#pragma unroll
        for (int s = 0; s < KC / 2; s++) {
            const float* pa = bA + 2 * s * PLANE + aoff0;
            unsigned a0 = __float_as_uint(pa[0]);
            unsigned a1 = __float_as_uint(pa[1]);
            unsigned a2 = __float_as_uint(pa[PLANE]);
            unsigned a3 = __float_as_uint(pa[PLANE + 1]);
            unsigned c0 = __float_as_uint(pa[16]);
            unsigned c1 = __float_as_uint(pa[17]);
            unsigned c2 = __float_as_uint(pa[PLANE + 16]);
            unsigned c3 = __float_as_uint(pa[PLANE + 17]);
            const float2* pb = bB + s * NT * 32 + lane;
#pragma unroll
            for (int nt = 0; nt < NT; nt++) {
                float2 bb = pb[nt * 32];
                unsigned bx0 = __float_as_uint(bb.x), bx1 = __float_as_uint(bb.y);
                mma_tf32(acc[nt],     a0, a1, a2, a3, bx0, bx1);
                mma_tf32(acc[nt] + 4, c0, c1, c2, c3, bx0, bx1);
            }
        }
        __syncthreads();
    }

    const int ho = 2 * (h0 + mr) + ph;
#pragma unroll
    for (int nt = 0; nt < NT; nt++) {
        int n0 = (coh * NT + nt) * 8 + 2 * (lane & 3);
#pragma unroll
        for (int t = 0; t < 2; t++)
#pragma unroll
            for (int j = 0; j < 4; j++) {
                int n  = n0 + (j & 1);
                int wi = colq + t * 16 + (j >> 1);
                int wo = 2 * wi + pw;
                float v = acc[nt][t * 4 + j];
                v = v > 0.0f ? v : 0.0f;
                if (RND) v = cvt_tf32(v);
                out[((size_t)(b * CO + n) * HOUT + ho) * WOUT + wo] = v;
            }
    }
}

// ================= MMA conv2 4x4 stride-2, M=32/warp, NT=4 via CO split =================
template<int CI, int CO, int COSPLIT, int HIN, int WIN, int KC, bool RND>
__global__ void __launch_bounds__(256, 3)
conv2_mma_k(const float* __restrict__ in, const float2* __restrict__ wf,
            const float* __restrict__ bias, float* __restrict__ out) {
    constexpr int MH = 4, MW = 64;
    constexpr int R = 2 * MH + 2, MWP = 2 * MW + 2;   // 10, 130
    constexpr int NTF = CO / 8;
    constexpr int NT = NTF / COSPLIT;
    constexpr int PLANE = R * MWP;
    constexpr int ASZ = KC * PLANE;
    constexpr int BSZ = KC * 2 * NT * 32;             // float2
    constexpr int SCHUNK = NT * 16;
    constexpr int NC = CI / KC;
    constexpr int HOUT = HIN / 2, WOUT = WIN / 2;
    extern __shared__ float sm[];
    float*  sA = sm;
    float2* sB = (float2*)(sm + 2 * ASZ);

    const int coh = blockIdx.x & (COSPLIT - 1);
    const int tile = blockIdx.x / COSPLIT;
    const int tiles_h = HOUT / MH;
    const int h0 = (tile % tiles_h) * MH;
    const int b  = tile / tiles_h;
    const int warp = threadIdx.x >> 5, lane = threadIdx.x & 31;
    const int kw = lane & 3;
    const int mbase = warp * 32;
    const int mr = mbase / MW;
    const int colq = (mbase % MW) + 2 * (lane >> 2);

    float acc[NT][8];
#pragma unroll
    for (int nt = 0; nt < NT; nt++) {
        float b0v = bias[(coh * NT + nt) * 8 + 2 * (lane & 3)];
        float b1v = bias[(coh * NT + nt) * 8 + 2 * (lane & 3) + 1];
#pragma unroll
        for (int t = 0; t < 2; t++) {
            acc[nt][4 * t + 0] = b0v; acc[nt][4 * t + 1] = b1v;
            acc[nt][4 * t + 2] = b0v; acc[nt][4 * t + 3] = b1v;
        }
    }

    const float* inb = in + (size_t)b * CI * HIN * WIN;
    const char*  wpB = (const char*)wf + ((size_t)coh * NT * 32) * 8;
    const unsigned sAu = smem_u32(sA);
    const unsigned sBu = smem_u32(sB);

    auto stageA = [&](int ci0, int buf) {
        for (int i = threadIdx.x; i < ASZ; i += 256) {
            int ci_l = i / PLANE;
            int rem  = i % PLANE;
            int r = rem / MWP, c = rem % MWP;
            int gr = 2 * h0 + r - 1;
            int gc = c - 1;
            bool ok = (unsigned)gr < (unsigned)HIN && (unsigned)gc < (unsigned)WIN;
            const float* src = inb + (size_t)(ci0 + ci_l) * HIN * WIN
                               + (ok ? gr * WIN + gc : 0);
            cp_async4(sAu + (buf * ASZ + i) * 4, src, ok);
        }
    };
    auto stageB = [&](int ci0, int buf) {
        for (int i = threadIdx.x; i < BSZ / 2; i += 256) {
            int s_k = i / SCHUNK, r = i % SCHUNK;
            const char* src = wpB + ((size_t)(ci0 * 2 + s_k) * NTF * 32) * 8 + r * 16;
            cp_async16(sBu + buf * BSZ * 8 + i * 16, src);
        }
    };

    stageA(0, 0); stageB(0, 0); cp_commit();
    for (int c = 0; c < NC; c++) {
        int buf = c & 1;
        if (c + 1 < NC) {
            stageA((c + 1) * KC, buf ^ 1);
            stageB((c + 1) * KC, buf ^ 1);
            cp_commit();
            cp_wait<1>();
        } else {
            cp_wait<0>();
        }
        __syncthreads();
        const float*  bA = sA + buf * ASZ;
        const float2* bB = sB + buf * BSZ;
#pragma unroll
        for (int s = 0; s < 2 * KC; s++) {
            int ci_l = s >> 1, th = s & 1;
            const float* pa = bA + ci_l * PLANE + (2 * mr + 2 * th) * MWP
                              + 2 * colq + kw;
            unsigned a0 = __float_as_uint(pa[0]);
            unsigned a1 = __float_as_uint(pa[2]);
            unsigned a2 = __float_as_uint(pa[MWP]);
            unsigned a3 = __float_as_uint(pa[MWP + 2]);
            unsigned c0 = __float_as_uint(pa[32]);
            unsigned c1 = __float_as_uint(pa[34]);
            unsigned c2 = __float_as_uint(pa[MWP + 32]);
            unsigned c3 = __float_as_uint(pa[MWP + 34]);
            const float2* pb = bB + s * NT * 32 + lane;
#pragma unroll
            for (int nt = 0; nt < NT; nt++) {
                float2 bb = pb[nt * 32];
                unsigned bx0 = __float_as_uint(bb.x), bx1 = __float_as_uint(bb.y);
                mma_tf32(acc[nt],     a0, a1, a2, a3, bx0, bx1);
                mma_tf32(acc[nt] + 4, c0, c1, c2, c3, bx0, bx1);
            }
        }
        __syncthreads();
    }

    const int ho = h0 + mr;
#pragma unroll
    for (int nt = 0; nt < NT; nt++) {
        int n0 = (coh * NT + nt) * 8 + 2 * (lane & 3);
#pragma unroll
        for (int t = 0; t < 2; t++)
#pragma unroll
            for (int j = 0; j < 4; j++) {
                int n  = n0 + (j & 1);
                int wo = colq + t * 16 + (j >> 1);
                float v = acc[nt][t * 4 + j];
                v = v > 0.0f ? v : 0.0f;
                if (RND) v = cvt_tf32(v);
                out[((size_t)(b * CO + n) * HOUT + ho) * WOUT + wo] = v;
            }
    }
}

// ================= MMA conv3x3 stride-1 (c3), M=32/warp, NT=4 via CO split =================
template<int CI, int CO, int COSPLIT, int HW, int KC>
__global__ void __launch_bounds__(256, 3)
conv3_mma_k(const float* __restrict__ in, const float2* __restrict__ wf,
            const float* __restrict__ bias, float* __restrict__ out) {
    constexpr int MH = 4, MW = 64;
    constexpr int R = MH + 2;                // 6 input rows
    constexpr int MWP = 80;
    constexpr int NTF = CO / 8;
    constexpr int NT = NTF / COSPLIT;
    constexpr int PLANE = R * MWP;
    constexpr int ASZ = KC * PLANE;
    constexpr int BSZ = (KC / 2) * 3 * NT * 32;   // float2
    constexpr int SCHUNK = NT * 16;
    constexpr int NC = CI / KC;
    extern __shared__ float sm[];
    float*  sA = sm;
    float2* sB = (float2*)(sm + 2 * ASZ);

    const int coh = blockIdx.x & (COSPLIT - 1);
    const int tile = blockIdx.x / COSPLIT;
    const int tiles_h = HW / MH;
    const int h0 = (tile % tiles_h) * MH;
    const int b  = tile / tiles_h;
    const int warp = threadIdx.x >> 5, lane = threadIdx.x & 31;
    const int mbase = warp * 32;
    const int mr = mbase / MW;
    const int colq = (mbase % MW) + 2 * (lane >> 2);

    float acc[NT][8];
#pragma unroll
    for (int nt = 0; nt < NT; nt++) {
        float b0v = bias[(coh * NT + nt) * 8 + 2 * (lane & 3)];
        float b1v = bias[(coh * NT + nt) * 8 + 2 * (lane & 3) + 1];
#pragma unroll
        for (int t = 0; t < 2; t++) {
            acc[nt][4 * t + 0] = b0v; acc[nt][4 * t + 1] = b1v;
            acc[nt][4 * t + 2] = b0v; acc[nt][4 * t + 3] = b1v;
        }
    }

    const float* inb = in + (size_t)b * CI * HW * HW;
    const char*  wpB = (const char*)wf + ((size_t)coh * NT * 32) * 8;
    const unsigned sAu = smem_u32(sA);
    const unsigned sBu = smem_u32(sB);

    auto stageA = [&](int ci0, int buf) {
        for (int i = threadIdx.x; i < ASZ; i += 256) {
            int ci_l = i / PLANE;
            int rem  = i % PLANE;
            int r = rem / MWP, c = rem % MWP;
            int gr = h0 + r - 1;
            int gc = c - 1;
            bool ok = (unsigned)gr < (unsigned)HW && (unsigned)gc < (unsigned)HW;
            const float* src = inb + (size_t)(ci0 + ci_l) * HW * HW
                               + (ok ? gr * HW + gc : 0);
            cp_async4(sAu + (buf * ASZ + i) * 4, src, ok);
        }
    };
    auto stageB = [&](int ci0, int buf) {
        for (int i = threadIdx.x; i < BSZ / 2; i += 256) {
            int sg = i / SCHUNK, r = i % SCHUNK;
            const char* src = wpB + ((size_t)((ci0 / 2) * 3 + sg) * NTF * 32) * 8 + r * 16;
            cp_async16(sBu + buf * BSZ * 8 + i * 16, src);
        }
    };

    stageA(0, 0); stageB(0, 0); cp_commit();
    for (int c = 0; c < NC; c++) {
        int buf = c & 1;
        if (c + 1 < NC) {
            stageA((c + 1) * KC, buf ^ 1);
            stageB((c + 1) * KC, buf ^ 1);
            cp_commit();
            cp_wait<1>();
        } else {
            cp_wait<0>();
        }
        __syncthreads();
        const float*  bA = sA + buf * ASZ;
        const float2* bB = sB + buf * BSZ;
#pragma unroll
        for (int s = 0; s < KC / 2; s++) {
#pragma unroll
            for (int g = 0; g < 3; g++) {
                const float* pa = bA + 2 * s * PLANE + (mr + g) * MWP
                                  + colq + (lane & 3);
                unsigned a0 = __float_as_uint(pa[0]);
                unsigned a1 = __float_as_uint(pa[1]);
                unsigned a2 = __float_as_uint(pa[PLANE]);
                unsigned a3 = __float_as_uint(pa[PLANE + 1]);
                unsigned c0 = __float_as_uint(pa[16]);
                unsigned c1 = __float_as_uint(pa[17]);
                unsigned c2 = __float_as_uint(pa[PLANE + 16]);
                unsigned c3 = __float_as_uint(pa[PLANE + 17]);
                const float2* pb = bB + (s * 3 + g) * NT * 32 + lane;
#pragma unroll
                for (int nt = 0; nt < NT; nt++) {
                    float2 bb = pb[nt * 32];
                    unsigned bx0 = __float_as_uint(bb.x), bx1 = __float_as_uint(bb.y);
                    mma_tf32(acc[nt],     a0, a1, a2, a3, bx0, bx1);
                    mma_tf32(acc[nt] + 4, c0, c1, c2, c3, bx0, bx1);
                }
            }
        }
        __syncthreads();
    }

    const int ho = h0 + mr;
#pragma unroll
    for (int nt = 0; nt < NT; nt++) {
        int n0 = (coh * NT + nt) * 8 + 2 * (lane & 3);
#pragma unroll
        for (int t = 0; t < 2; t++)
#pragma unroll
            for (int j = 0; j < 4; j++) {
                int n  = n0 + (j & 1);
                int wo = colq + t * 16 + (j >> 1);
                float v = acc[nt][t * 4 + j];
                v = v > 0.0f ? v : 0.0f;
                out[((size_t)(b * CO + n) * HW + ho) * HW + wo] = v;
            }
    }
}

// ---------------- conv + relu, f32x2 (c1) ----------------
template<int CI, int K, int CO, int COT, int WT,
         int HIN, int WIN, int HOUT, int WOUT, int ST, int PD, bool RND>
__global__ void conv_f2_k(const float* __restrict__ in, const float* __restrict__ wt,
                          const float* __restrict__ bias, float* __restrict__ out) {
    extern __shared__ float ws[];
    const int cob = blockIdx.y * COT;
    const int WROWS = CI * K * K;
    for (int i = threadIdx.x; i < WROWS * COT; i += 256) {
        int r = i / COT, c = i % COT;
        ws[i] = wt[r * CO + cob + c];
    }
    __syncthreads();

    const int warp = threadIdx.x >> 5, lane = threadIdx.x & 31;
    const int SPR = WOUT / (32 * WT);
    int seg = blockIdx.x * 8 + warp;
    int s   = seg % SPR;
    int row = seg / SPR;
    int h   = row % HOUT;
    int b   = row / HOUT;

    int wcol[WT];
#pragma unroll
    for (int k = 0; k < WT; k++) wcol[k] = s * 32 * WT + lane + 32 * k;

    unsigned long long acc[WT][COT / 2];
#pragma unroll
    for (int k = 0; k < WT; k++)
#pragma unroll
        for (int j = 0; j < COT / 2; j++)
            acc[k][j] = pk(bias[cob + 2 * j], bias[cob + 2 * j + 1]);

    const float* inb = in + (size_t)b * CI * HIN * WIN;
#pragma unroll 2
    for (int ci = 0; ci < CI; ci++) {
        const float* inp = inb + (size_t)ci * HIN * WIN;
#pragma unroll
        for (int kh = 0; kh < K; kh++) {
            int hi = h * ST - PD + kh;
            if ((unsigned)hi >= (unsigned)HIN) continue;
            const float* rp = inp + hi * WIN;
#pragma unroll
            for (int kw = 0; kw < K; kw++) {
                const ulonglong2* wv = reinterpret_cast<const ulonglong2*>(
                    ws + (ci * (K * K) + kh * K + kw) * COT);
                unsigned long long vv[WT];
#pragma unroll
                for (int k = 0; k < WT; k++) {
                    int wi = wcol[k] * ST - PD + kw;
                    float v = ((unsigned)wi < (unsigned)WIN) ? rp[wi] : 0.0f;
                    vv[k] = pk2(v);
                }
#pragma unroll
                for (int j = 0; j < COT / 4; j++) {
                    ulonglong2 w2 = wv[j];
#pragma unroll
                    for (int k = 0; k < WT; k++) {
                        fma2(acc[k][2 * j], vv[k], w2.x);
                        fma2(acc[k][2 * j + 1], vv[k], w2.y);
                    }
                }
            }
        }
    }

    size_t obase = ((size_t)b * CO + cob) * HOUT * WOUT + (size_t)h * WOUT;
#pragma unroll
    for (int k = 0; k < WT; k++)
#pragma unroll
        for (int j = 0; j < COT / 2; j++) {
            float2 r = up2(acc[k][j]);
            float v0 = r.x > 0.0f ? r.x : 0.0f;
            float v1 = r.y > 0.0f ? r.y : 0.0f;
            if (RND) { v0 = cvt_tf32(v0); v1 = cvt_tf32(v1); }
            out[obase + (size_t)(2 * j) * HOUT * WOUT + wcol[k]] = v0;
            out[obase + (size_t)(2 * j + 1) * HOUT * WOUT + wcol[k]] = v1;
        }
}

// ---------------- small-CO stride-1 conv + sigmoid (dc3), f32x2 spatial pairs ----------------
template<int CI, int K, int CO, int WT, int HIN, int WIN, int PD>
__global__ void conv_sig_k(const float* __restrict__ in, const float* __restrict__ wt,
                           const float* __restrict__ bias, float* __restrict__ out) {
    constexpr int HOUT = HIN, WOUT = WIN;
    extern __shared__ float ws[];
    for (int i = threadIdx.x; i < CI * K * K * CO; i += 256) ws[i] = wt[i];
    __syncthreads();

    const int warp = threadIdx.x >> 5, lane = threadIdx.x & 31;
    const int SPR = WOUT / (32 * WT);
    int seg = blockIdx.x * 8 + warp;
    int s   = seg % SPR;
    int row = seg / SPR;
    int h   = row % HOUT;
    int b   = row / HOUT;

    int wcol[WT];
#pragma unroll
    for (int k = 0; k < WT; k++) wcol[k] = s * 32 * WT + lane + 32 * k;

    unsigned long long acc[WT / 2][CO];
#pragma unroll
    for (int p = 0; p < WT / 2; p++)
#pragma unroll
        for (int c = 0; c < CO; c++) acc[p][c] = pk2(bias[c]);

    const float* inb = in + (size_t)b * CI * HIN * WIN;
#pragma unroll 2
    for (int ci = 0; ci < CI; ci++) {
        const float* inp = inb + (size_t)ci * HIN * WIN;
#pragma unroll
        for (int kh = 0; kh < K; kh++) {
            int hi = h - PD + kh;
            if ((unsigned)hi >= (unsigned)HIN) continue;
            const float* rp = inp + hi * WIN;
#pragma unroll
            for (int kw = 0; kw < K; kw++) {
                const float* wr = ws + (ci * (K * K) + kh * K + kw) * CO;
                float v[WT];
#pragma unroll
                for (int k = 0; k < WT; k++) {
                    int wi = wcol[k] - PD + kw;
                    v[k] = ((unsigned)wi < (unsigned)WIN) ? rp[wi] : 0.0f;
                }
#pragma unroll
                for (int c = 0; c < CO; c++) {
                    unsigned long long w2 = pk2(wr[c]);
#pragma unroll
                    for (int p = 0; p < WT / 2; p++)
                        fma2(acc[p][c], pk(v[2 * p], v[2 * p + 1]), w2);
                }
            }
        }
    }

    size_t obase = (size_t)b * CO * HOUT * WOUT + (size_t)h * WOUT;
#pragma unroll
    for (int p = 0; p < WT / 2; p++)
#pragma unroll
        for (int c = 0; c < CO; c++) {
            float2 r = up2(acc[p][c]);
            float v0 = 1.0f / (1.0f + __expf(-r.x));
            float v1 = 1.0f / (1.0f + __expf(-r.y));
            out[obase + (size_t)c * HOUT * WOUT + wcol[2 * p]] = v0;
            out[obase + (size_t)c * HOUT * WOUT + wcol[2 * p + 1]] = v1;
        }
}

// ---------------- vector quantize + q materialization (gather fused) ----------------
__global__ void vq_k(const float* __restrict__ emb, const float* __restrict__ z,
                     float* __restrict__ q) {
    extern __shared__ float sm[];
    float4* sp4 = (float4*)sm;               // 256*32 float4 paired codebook
    float2* sn2 = (float2*)(sm + 512 * 64);  // 256 norm pairs
    for (int i = threadIdx.x; i < 512 * 64; i += blockDim.x) {
        int k = i >> 6, j = i & 63;
        int dst = ((k >> 1) * 32 + (j >> 1)) * 4 + (j & 1) * 2 + (k & 1);
        sm[dst] = emb[i];
    }
    __syncthreads();
    for (int kp = threadIdx.x; kp < 256; kp += blockDim.x) {
        float sx = 0.0f, sy = 0.0f;
#pragma unroll
        for (int j2 = 0; j2 < 32; j2++) {
            float4 e = sp4[kp * 32 + j2];
            sx += e.x * e.x + e.z * e.z;
            sy += e.y * e.y + e.w * e.w;
        }
        sn2[kp] = make_float2(sx, sy);
    }
    __syncthreads();

    int n = blockIdx.x * blockDim.x + threadIdx.x;
    int b  = n >> 12;
    int hw = n & 4095;
    const float* zp = z + (size_t)b * 262144 + hw;
    float zr[64];
#pragma unroll
    for (int j = 0; j < 64; j++) zr[j] = zp[(size_t)j * 4096];

    float best = 3.4e38f;
    int bi = 0;
    for (int kp = 0; kp < 256; kp++) {
        const float4* ep = sp4 + kp * 32;
        unsigned long long dp = pk(0.0f, 0.0f);
#pragma unroll
        for (int j2 = 0; j2 < 32; j2++) {
            float4 e = ep[j2];
            fma2(dp, pk2(zr[2 * j2]),     pk(e.x, e.y));
            fma2(dp, pk2(zr[2 * j2 + 1]), pk(e.z, e.w));
        }
        float2 d2 = up2(dp);
        float2 nn = sn2[kp];
        float dx = nn.x - 2.0f * d2.x;
        if (dx < best) { best = dx; bi = 2 * kp; }
        float dy = nn.y - 2.0f * d2.y;
        if (dy < best) { best = dy; bi = 2 * kp + 1; }
    }

    float* qp = q + (size_t)b * 262144 + hw;
    float ls = 0.0f;
#pragma unroll
    for (int j = 0; j < 64; j++) {
        float e = sm[((bi >> 1) * 32 + (j >> 1)) * 4 + (j & 1) * 2 + (bi & 1)];
        qp[(size_t)j * 4096] = cvt_tf32(e);
        float df = e - zr[j];
        ls += df * df;
    }
#pragma unroll
    for (int o = 16; o > 0; o >>= 1) ls += __shfl_xor_sync(0xffffffffu, ls, o);
    if ((threadIdx.x & 31) == 0) atomicAdd(&g_loss, ls);
}

// ---------------- host ----------------
static float* sym_addr(const void* sym) {
    void* p = nullptr;
    cudaGetSymbolAddress(&p, sym);
    return (float*)p;
}

extern "C" void kernel_launch(void* const* d_in, const int* in_sizes, int n_in,
                              void* d_out, int out_size) {
    const float* x   = (const float*)d_in[0];
    const float* w1  = (const float*)d_in[1];
    const float* b1  = (const float*)d_in[2];
    const float* w2  = (const float*)d_in[3];
    const float* b2  = (const float*)d_in[4];
    const float* w3  = (const float*)d_in[5];
    const float* b3  = (const float*)d_in[6];
    const float* emb = (const float*)d_in[7];
    const float* dw1 = (const float*)d_in[8];
    const float* db1 = (const float*)d_in[9];
    const float* dw2 = (const float*)d_in[10];
    const float* db2 = (const float*)d_in[11];
    const float* dw3 = (const float*)d_in[12];
    const float* db3 = (const float*)d_in[13];
    float* out = (float*)d_out;

    float*  h1   = sym_addr(g_h1);
    float*  h2   = sym_addr(g_h2);
    float*  z    = sym_addr(g_z);
    float*  q    = sym_addr(g_q);
    float*  d1   = sym_addr(g_d1);
    float*  d2   = sym_addr(g_d2);
    float*  wt1  = sym_addr(g_wt1);
    float*  wt3d = sym_addr(g_wt3d);
    float2* pw1f = (float2*)sym_addr(g_pw1f);
    float2* pw2f = (float2*)sym_addr(g_pw2f);
    float2* cw2f = (float2*)sym_addr(g_cw2f);
    float2* cw3f = (float2*)sym_addr(g_cw3f);

    auto c1  = conv_f2_k<3, 4, 64, 32, 2, 256, 256, 128, 128, 2, 1, true>;
    auto c2m = conv2_mma_k<64, 128, 4, 128, 128, 4, true>;
    auto c3m = conv3_mma_k<128, 64, 2, 64, 8>;
    auto dc1 = deconv_mma_k<64, 128, 4, 4, 64, 80, 64, 64, 8, true>;
    auto dc2 = deconv_mma_k<128, 64, 2, 2, 128, 144, 128, 128, 8, false>;
    auto dc3 = conv_sig_k<64, 3, 3, 4, 256, 256, 1>;

    // smem sizes (NT=4 everywhere)
    const int smem_c2  = 2 * (4 * 10 * 130) * 4 + 2 * (4 * 2 * 4 * 32) * 8;  // 57984
    const int smem_c3  = 2 * (8 * 6 * 80) * 4 + 2 * (4 * 3 * 4 * 32) * 8;    // 55296
    const int smem_dc1 = 2 * (8 * 5 * 80) * 4 + 2 * (4 * 4 * 32) * 8;        // 33792
    const int smem_dc2 = 2 * (8 * 3 * 144) * 4 + 2 * (4 * 4 * 32) * 8;       // 35840
    const int smem_vq  = 512 * 64 * 4 + 256 * 8;                             // 133120

    cudaFuncSetAttribute(c2m, cudaFuncAttributeMaxDynamicSharedMemorySize, smem_c2);
    cudaFuncSetAttribute(c3m, cudaFuncAttributeMaxDynamicSharedMemorySize, smem_c3);
    cudaFuncSetAttribute(dc1, cudaFuncAttributeMaxDynamicSharedMemorySize, smem_dc1);
    cudaFuncSetAttribute(dc2, cudaFuncAttributeMaxDynamicSharedMemorySize, smem_dc2);
    cudaFuncSetAttribute(vq_k, cudaFuncAttributeMaxDynamicSharedMemorySize, smem_vq);

    // launch 1: fused repack (+ loss zero)
    repack_all_k<<<(217792 + 255) / 256, 256>>>(w1, w2, w3, dw1, dw2, dw3,
                                                wt1, cw2f, cw3f, pw1f, pw2f, wt3d);

    // launch 2-4: encoder
    c1<<<dim3(1024, 2), 256, 3 * 16 * 32 * 4>>>(x, wt1, b1, h1);
    // c2m grid = COSPLIT(4) * tiles_h(16) * B(32) = 2048  [R8 bug: was 1024]
    c2m<<<dim3(4 * 16 * 32), 256, smem_c2>>>(h1, cw2f, b2, h2);
    c3m<<<dim3(2 * 16 * 32), 256, smem_c3>>>(h2, cw3f, b3, z);

    // launch 5: vector quantize (writes q directly)
    vq_k<<<512, 256, smem_vq>>>(emb, z, q);

    // launch 6-8: decoder (parity+coh on blockIdx.x -> wave-adjacent, L2-hot input)
    dc1<<<dim3(16, 16 * 32), 256, smem_dc1>>>(q, pw1f, db1, d1);
    dc2<<<dim3(8, 64 * 32), 256, smem_dc2>>>(d1, pw2f, db2, d2);
    dc3<<<dim3(2048, 1), 256, 64 * 9 * 3 * 4>>>(d2, wt3d, db3, out);

    finalize_k<<<1, 1>>>(out, out_size - 1);
}

// round 12
// speedup vs baseline: 1.2220x; 1.2220x over previous
#include <cuda_runtime.h>
#include <math.h>

// ---------------- scratch (device globals: allocation-free rule) ----------------
__device__ float g_h1[32u * 64 * 128 * 128];   // after conv1+relu   (NCHW, tf32-rounded)
__device__ float g_h2[32u * 128 * 64 * 64];    // after conv2+relu   (NCHW, tf32-rounded)
__device__ float g_z [32u * 64 * 64 * 64];     // after conv3+relu   (NCHW, fp32)
__device__ float g_q [32u * 64 * 64 * 64];     // quantized          (NCHW, tf32-rounded)
__device__ float g_d1[32u * 128 * 128 * 128];  // after deconv1+relu (NCHW, tf32-rounded)
__device__ float g_d2[32u * 64 * 256 * 256];   // after deconv2+relu (NCHW, fp32)

// repacked weights
__device__ float  g_wt1 [64 * 3 * 16];          // c1 scalar path
__device__ float  g_wt3d[3 * 64 * 9];           // dc3 flipped -> plain conv
__device__ float2 g_pw1f[4 * 32 * 16 * 32];     // dc1 B [p][s][ntf][lane]
__device__ float2 g_pw2f[4 * 64 * 8 * 32];      // dc2 B
__device__ float2 g_cw2f[128 * 16 * 32];        // c2  B [s][ntf][lane]
__device__ float2 g_cw3f[64 * 3 * 8 * 32];      // c3  B (12 taps, kw=3 zeroed)

__device__ float g_loss;

// ---------------- helpers ----------------
__device__ __forceinline__ float cvt_tf32(float x) {
    asm("cvt.rna.tf32.f32 %0, %0;" : "+f"(x));
    return x;
}
__device__ __forceinline__ unsigned long long pk2(float x) {
    unsigned long long r;
    asm("mov.b64 %0, {%1, %1};" : "=l"(r) : "f"(x));
    return r;
}
__device__ __forceinline__ unsigned long long pk(float x, float y) {
    unsigned long long r;
    asm("mov.b64 %0, {%1, %2};" : "=l"(r) : "f"(x), "f"(y));
    return r;
}
__device__ __forceinline__ void fma2(unsigned long long& d,
                                     unsigned long long a, unsigned long long b) {
    asm("fma.rn.f32x2 %0, %1, %2, %0;" : "+l"(d) : "l"(a), "l"(b));
}
__device__ __forceinline__ float2 up2(unsigned long long v) {
    float2 f;
    asm("mov.b64 {%0, %1}, %2;" : "=f"(f.x), "=f"(f.y) : "l"(v));
    return f;
}
__device__ __forceinline__ void mma_tf32(float* c, unsigned a0, unsigned a1,
                                         unsigned a2, unsigned a3,
                                         unsigned b0, unsigned b1) {
    asm volatile(
        "mma.sync.aligned.m16n8k8.row.col.f32.tf32.tf32.f32 "
        "{%0,%1,%2,%3}, {%4,%5,%6,%7}, {%8,%9}, {%0,%1,%2,%3};"
        : "+f"(c[0]), "+f"(c[1]), "+f"(c[2]), "+f"(c[3])
        : "r"(a0), "r"(a1), "r"(a2), "r"(a3), "r"(b0), "r"(b1));
}
__device__ __forceinline__ unsigned smem_u32(const void* p) {
    return (unsigned)__cvta_generic_to_shared(p);
}
__device__ __forceinline__ void cp_async4(unsigned dst, const void* src, bool pred) {
    int sz = pred ? 4 : 0;
    asm volatile("cp.async.ca.shared.global [%0], [%1], 4, %2;"
                 :: "r"(dst), "l"(src), "r"(sz));
}
__device__ __forceinline__ void cp_async16(unsigned dst, const void* src) {
    asm volatile("cp.async.cg.shared.global [%0], [%1], 16;" :: "r"(dst), "l"(src));
}
__device__ __forceinline__ void cp_commit() {
    asm volatile("cp.async.commit_group;");
}
template<int N> __device__ __forceinline__ void cp_wait() {
    asm volatile("cp.async.wait_group %0;" :: "n"(N));
}

// ---------------- fused weight repack (single launch; also zeroes loss) ----------------
__global__ void repack_all_k(const float* __restrict__ w1, const float* __restrict__ w2,
                             const float* __restrict__ w3, const float* __restrict__ dw1,
                             const float* __restrict__ dw2, const float* __restrict__ dw3,
                             float* __restrict__ wt1, float2* __restrict__ cw2f,
                             float2* __restrict__ cw3f, float2* __restrict__ pw1f,
                             float2* __restrict__ pw2f, float* __restrict__ wt3d) {
    int i = blockIdx.x * blockDim.x + threadIdx.x;
    if (i == 0) g_loss = 0.0f;

    if (i < 3072) {                       // c1 [(ci*16+t)*64+co]
        int co = i / 48, r = i % 48;
        wt1[r * 64 + co] = w1[i];
        return;
    }
    i -= 3072;
    if (i < 65536) {                      // c2 B frag order, NT=16
        int lane = i & 31;
        int t1 = i >> 5;
        int nt = t1 % 16;
        int s  = t1 / 16;
        int ci = s >> 1, th = s & 1;
        int kw = lane & 3;
        int co = nt * 8 + (lane >> 2);
        float v0 = w2[((co * 64 + ci) * 4 + 2 * th) * 4 + kw];
        float v1 = w2[((co * 64 + ci) * 4 + 2 * th + 1) * 4 + kw];
        cw2f[i] = make_float2(cvt_tf32(v0), cvt_tf32(v1));
        return;
    }
    i -= 65536;
    if (i < 49152) {                      // c3 B frag order, NT=8
        int lane = i & 31;
        int t1 = i >> 5;
        int nt = t1 % 8;
        int t2 = t1 / 8;
        int g  = t2 % 3;
        int s  = t2 / 3;
        int kw = lane & 3;
        int co = nt * 8 + (lane >> 2);
        float v0 = 0.0f, v1 = 0.0f;
        if (kw < 3) {
            v0 = w3[((co * 128 + 2 * s) * 3 + g) * 3 + kw];
            v1 = w3[((co * 128 + 2 * s + 1) * 3 + g) * 3 + kw];
        }
        cw3f[i] = make_float2(cvt_tf32(v0), cvt_tf32(v1));
        return;
    }
    i -= 49152;
    if (i < 65536) {                      // dc1 B parity-frag order, NT=16
        int lane = i & 31;
        int t1 = i >> 5;
        int nt = t1 % 16;
        int t2 = t1 / 16;
        int s  = t2 % 32;
        int p  = t2 / 32;
        int tap = lane & 3;
        int a = tap >> 1, bt = tap & 1;
        int ph = p >> 1, pwb = p & 1;
        int kh = ph ? (a ? 0 : 2) : (a ? 3 : 1);
        int kw = pwb ? (bt ? 0 : 2) : (bt ? 3 : 1);
        int co = nt * 8 + (lane >> 2);
        float v0 = dw1[(((2 * s) * 128 + co) * 4 + kh) * 4 + kw];
        float v1 = dw1[(((2 * s + 1) * 128 + co) * 4 + kh) * 4 + kw];
        pw1f[i] = make_float2(cvt_tf32(v0), cvt_tf32(v1));
        return;
    }
    i -= 65536;
    if (i < 32768) {                      // dc2 B parity-frag order, NT=8
        int lane = i & 31;
        int t1 = i >> 5;
        int nt = t1 % 8;
        int t2 = t1 / 8;
        int s  = t2 % 64;
        int p  = t2 / 64;
        int tap = lane & 3;
        int a = tap >> 1, bt = tap & 1;
        int ph = p >> 1, pwb = p & 1;
        int kh = ph ? (a ? 0 : 2) : (a ? 3 : 1);
        int kw = pwb ? (bt ? 0 : 2) : (bt ? 3 : 1);
        int co = nt * 8 + (lane >> 2);
        float v0 = dw2[(((2 * s) * 64 + co) * 4 + kh) * 4 + kw];
        float v1 = dw2[(((2 * s + 1) * 64 + co) * 4 + kh) * 4 + kw];
        pw2f[i] = make_float2(cvt_tf32(v0), cvt_tf32(v1));
        return;
    }
    i -= 32768;
    if (i < 1728) {                       // dc3 flip -> plain conv
        int ci = i / 27;
        int r  = i % 27;
        int co = r / 9;
        int t  = r % 9;
        int kh = t / 3, kw = t % 3;
        int tf = (2 - kh) * 3 + (2 - kw);
        wt3d[(ci * 9 + tf) * 3 + co] = dw3[i];
    }
}

__global__ void finalize_k(float* __restrict__ out, int loss_idx) {
    out[loss_idx] = 1.25f * g_loss * (1.0f / 8388608.0f);
}

// ================= MMA stride-2 deconv, parity-decomposed, pipelined (R6 geometry) =================
// blockIdx.x = parity (fastest-varying -> 4 parity blocks of a tile are wave-adjacent).
template<int CI, int CO, int MH, int MW, int MWP, int HIN, int WIN, int KC, bool RND>
__global__ void deconv_mma_k(const float* __restrict__ in, const float2* __restrict__ wf,
                             const float* __restrict__ bias, float* __restrict__ out) {
    constexpr int R = MH + 1;
    constexpr int NT = CO / 8;
    constexpr int PLANE = R * MWP;
    constexpr int ASZ = KC * PLANE;
    constexpr int BSZ = (KC / 2) * NT * 32;
    constexpr int NC = CI / KC;
    constexpr int HOUT = 2 * HIN, WOUT = 2 * WIN;
    extern __shared__ float sm[];
    float*  sA = sm;
    float2* sB = (float2*)(sm + 2 * ASZ);

    const int p  = blockIdx.x, ph = p >> 1, pw = p & 1;
    const int tiles_h = HIN / MH;
    const int h0 = (blockIdx.y % tiles_h) * MH;
    const int b  = blockIdx.y / tiles_h;
    const int warp = threadIdx.x >> 5, lane = threadIdx.x & 31;
    const int tap = lane & 3;
    const int a = tap >> 1, bt = tap & 1;
    const int roff = ph ? a : 1 - a;
    const int coff = pw ? bt : 1 - bt;
    const int mbase = warp * 16;
    const int mr = mbase / MW;
    const int colq = (mbase % MW) + 2 * (lane >> 2);
    const int aoff0 = (mr + roff) * MWP + colq + coff;

    float acc[NT][4];
#pragma unroll
    for (int nt = 0; nt < NT; nt++) {
        float b0v = bias[nt * 8 + 2 * (lane & 3)];
        float b1v = bias[nt * 8 + 2 * (lane & 3) + 1];
        acc[nt][0] = b0v; acc[nt][1] = b1v; acc[nt][2] = b0v; acc[nt][3] = b1v;
    }

    const float*  inb = in + (size_t)b * CI * HIN * WIN;
    const float2* wpb = wf + (size_t)p * (CI / 2) * NT * 32;
    const unsigned sAu = smem_u32(sA);
    const unsigned sBu = smem_u32(sB);

    auto stageA = [&](int ci0, int buf) {
        for (int i = threadIdx.x; i < ASZ; i += 256) {
            int ci_l = i / PLANE;
            int rem  = i % PLANE;
            int r = rem / MWP, c = rem % MWP;
            int gr = h0 + r - (ph ? 0 : 1);
            int gc = c - (pw ? 0 : 1);
            bool ok = (unsigned)gr < (unsigned)HIN && (unsigned)gc < (unsigned)WIN;
            const float* src = inb + (size_t)(ci0 + ci_l) * HIN * WIN
                               + (ok ? gr * WIN + gc : 0);
            cp_async4(sAu + (buf * ASZ + i) * 4, src, ok);
        }
    };
    auto stageB = [&](int ci0, int buf) {
        const char* src = (const char*)(wpb + (size_t)(ci0 / 2) * NT * 32);
        for (int i = threadIdx.x; i < BSZ / 2; i += 256)
            cp_async16(sBu + buf * BSZ * 8 + i * 16, src + i * 16);
    };

    stageA(0, 0); stageB(0, 0); cp_commit();
    for (int c = 0; c < NC; c++) {
        int buf = c & 1;
        if (c + 1 < NC) {
            stageA((c + 1) * KC, buf ^ 1);
            stageB((c + 1) * KC, buf ^ 1);
            cp_commit();
            cp_wait<1>();
        } else {
            cp_wait<0>();
        }
        __syncthreads();
        const float*  bA = sA + buf * ASZ;
        const float2* bB = sB + buf * BSZ;
#pragma unroll
        for (int s = 0; s < KC / 2; s++) {
            const float* pa = bA + 2 * s * PLANE + aoff0;
            unsigned a0 = __float_as_uint(pa[0]);
            unsigned a1 = __float_as_uint(pa[1]);
            unsigned a2 = __float_as_uint(pa[PLANE]);
            unsigned a3 = __float_as_uint(pa[PLANE + 1]);
            const float2* pb = bB + s * NT * 32 + lane;
#pragma unroll
            for (int nt = 0; nt < NT; nt++) {
                float2 bb = pb[nt * 32];
                mma_tf32(acc[nt], a0, a1, a2, a3,
                         __float_as_uint(bb.x), __float_as_uint(bb.y));
            }
        }
        __syncthreads();
    }

    const int ho = 2 * (h0 + mr) + ph;
#pragma unroll
    for (int nt = 0; nt < NT; nt++) {
        int n0 = nt * 8 + 2 * (lane & 3);
#pragma unroll
        for (int j = 0; j < 4; j++) {
            int n  = n0 + (j & 1);
            int wi = colq + (j >> 1);
            int wo = 2 * wi + pw;
            float v = acc[nt][j];
            v = v > 0.0f ? v : 0.0f;
            if (RND) v = cvt_tf32(v);
            out[((size_t)(b * CO + n) * HOUT + ho) * WOUT + wo] = v;
        }
    }
}

// ================= MMA conv2 4x4 stride-2, pipelined (R6 geometry, KC=2 for residency) =================
template<int CI, int CO, int HIN, int WIN, int KC, bool RND>
__global__ void conv2_mma_k(const float* __restrict__ in, const float2* __restrict__ wf,
                            const float* __restrict__ bias, float* __restrict__ out) {
    constexpr int MH = 2, MW = 64;
    constexpr int R = 6, MWP = 2 * MW + 2;
    constexpr int NT = CO / 8;
    constexpr int PLANE = R * MWP;
    constexpr int ASZ = KC * PLANE;
    constexpr int BSZ = KC * 2 * NT * 32;
    constexpr int NC = CI / KC;
    constexpr int HOUT = HIN / 2, WOUT = WIN / 2;
    extern __shared__ float sm[];
    float*  sA = sm;
    float2* sB = (float2*)(sm + 2 * ASZ);

    const int tiles_h = HOUT / MH;
    const int h0 = (blockIdx.x % tiles_h) * MH;
    const int b  = blockIdx.x / tiles_h;
    const int warp = threadIdx.x >> 5, lane = threadIdx.x & 31;
    const int kw = lane & 3;
    const int mbase = warp * 16;
    const int mr = mbase / MW;
    const int colq = (mbase % MW) + 2 * (lane >> 2);

    float acc[NT][4];
#pragma unroll
    for (int nt = 0; nt < NT; nt++) {
        float b0v = bias[nt * 8 + 2 * (lane & 3)];
        float b1v = bias[nt * 8 + 2 * (lane & 3) + 1];
        acc[nt][0] = b0v; acc[nt][1] = b1v; acc[nt][2] = b0v; acc[nt][3] = b1v;
    }

    const float* inb = in + (size_t)b * CI * HIN * WIN;
    const unsigned sAu = smem_u32(sA);
    const unsigned sBu = smem_u32(sB);

    auto stageA = [&](int ci0, int buf) {
        for (int i = threadIdx.x; i < ASZ; i += 256) {
            int ci_l = i / PLANE;
            int rem  = i % PLANE;
            int r = rem / MWP, c = rem % MWP;
            int gr = 2 * h0 + r - 1;
            int gc = c - 1;
            bool ok = (unsigned)gr < (unsigned)HIN && (unsigned)gc < (unsigned)WIN;
            const float* src = inb + (size_t)(ci0 + ci_l) * HIN * WIN
                               + (ok ? gr * WIN + gc : 0);
            cp_async4(sAu + (buf * ASZ + i) * 4, src, ok);
        }
    };
    auto stageB = [&](int ci0, int buf) {
        const char* src = (const char*)(wf + (size_t)(ci0 * 2) * NT * 32);
        for (int i = threadIdx.x; i < BSZ / 2; i += 256)
            cp_async16(sBu + buf * BSZ * 8 + i * 16, src + i * 16);
    };

    stageA(0, 0); stageB(0, 0); cp_commit();
    for (int c = 0; c < NC; c++) {
        int buf = c & 1;
        if (c + 1 < NC) {
            stageA((c + 1) * KC, buf ^ 1);
            stageB((c + 1) * KC, buf ^ 1);
            cp_commit();
            cp_wait<1>();
        } else {
            cp_wait<0>();
        }
        __syncthreads();
        const float*  bA = sA + buf * ASZ;
        const float2* bB = sB + buf * BSZ;
#pragma unroll
        for (int s = 0; s < 2 * KC; s++) {
            int ci_l = s >> 1, th = s & 1;
            const float* pa = bA + ci_l * PLANE + (2 * mr + 2 * th) * MWP
                              + 2 * colq + kw;
            unsigned a0 = __float_as_uint(pa[0]);
            unsigned a1 = __float_as_uint(pa[2]);
            unsigned a2 = __float_as_uint(pa[MWP]);
            unsigned a3 = __float_as_uint(pa[MWP + 2]);
            const float2* pb = bB + s * NT * 32 + lane;
#pragma unroll
            for (int nt = 0; nt < NT; nt++) {
                float2 bb = pb[nt * 32];
                mma_tf32(acc[nt], a0, a1, a2, a3,
                         __float_as_uint(bb.x), __float_as_uint(bb.y));
            }
        }
        __syncthreads();
    }

    const int ho = h0 + mr;
#pragma unroll
    for (int nt = 0; nt < NT; nt++) {
        int n0 = nt * 8 + 2 * (lane & 3);
#pragma unroll
        for (int j = 0; j < 4; j++) {
            int n  = n0 + (j & 1);
            int wo = colq + (j >> 1);
            float v = acc[nt][j];
            v = v > 0.0f ? v : 0.0f;
            if (RND) v = cvt_tf32(v);
            out[((size_t)(b * CO + n) * HOUT + ho) * WOUT + wo] = v;
        }
    }
}

// ================= MMA conv3x3 stride-1 (c3), taps padded to 12, pipelined (KC=4) =================
template<int CI, int CO, int HW, int KC>
__global__ void conv3_mma_k(const float* __restrict__ in, const float2* __restrict__ wf,
                            const float* __restrict__ bias, float* __restrict__ out) {
    constexpr int MH = 2, MW = 64;
    constexpr int R = MH + 2;
    constexpr int MWP = 80;
    constexpr int NT = CO / 8;
    constexpr int PLANE = R * MWP;
    constexpr int ASZ = KC * PLANE;
    constexpr int BSZ = (KC / 2) * 3 * NT * 32;
    constexpr int NC = CI / KC;
    extern __shared__ float sm[];
    float*  sA = sm;
    float2* sB = (float2*)(sm + 2 * ASZ);

    const int tiles_h = HW / MH;
    const int h0 = (blockIdx.x % tiles_h) * MH;
    const int b  = blockIdx.x / tiles_h;
    const int warp = threadIdx.x >> 5, lane = threadIdx.x & 31;
    const int mbase = warp * 16;
    const int mr = mbase / MW;
    const int colq = (mbase % MW) + 2 * (lane >> 2);

    float acc[NT][4];
#pragma unroll
    for (int nt = 0; nt < NT; nt++) {
        float b0v = bias[nt * 8 + 2 * (lane & 3)];
        float b1v = bias[nt * 8 + 2 * (lane & 3) + 1];
        acc[nt][0] = b0v; acc[nt][1] = b1v; acc[nt][2] = b0v; acc[nt][3] = b1v;
    }

    const float* inb = in + (size_t)b * CI * HW * HW;
    const unsigned sAu = smem_u32(sA);
    const unsigned sBu = smem_u32(sB);

    auto stageA = [&](int ci0, int buf) {
        for (int i = threadIdx.x; i < ASZ; i += 256) {
            int ci_l = i / PLANE;
            int rem  = i % PLANE;
            int r = rem / MWP, c = rem % MWP;
            int gr = h0 + r - 1;
            int gc = c - 1;
            bool ok = (unsigned)gr < (unsigned)HW && (unsigned)gc < (unsigned)HW;
            const float* src = inb + (size_t)(ci0 + ci_l) * HW * HW
                               + (ok ? gr * HW + gc : 0);
            cp_async4(sAu + (buf * ASZ + i) * 4, src, ok);
        }
    };
    auto stageB = [&](int ci0, int buf) {
        const char* src = (const char*)(wf + (size_t)(ci0 / 2) * 3 * NT * 32);
        for (int i = threadIdx.x; i < BSZ / 2; i += 256)
            cp_async16(sBu + buf * BSZ * 8 + i * 16, src + i * 16);
    };

    stageA(0, 0); stageB(0, 0); cp_commit();
    for (int c = 0; c < NC; c++) {
        int buf = c & 1;
        if (c + 1 < NC) {
            stageA((c + 1) * KC, buf ^ 1);
            stageB((c + 1) * KC, buf ^ 1);
            cp_commit();
            cp_wait<1>();
        } else {
            cp_wait<0>();
        }
        __syncthreads();
        const float*  bA = sA + buf * ASZ;
        const float2* bB = sB + buf * BSZ;
#pragma unroll
        for (int s = 0; s < KC / 2; s++) {
#pragma unroll
            for (int g = 0; g < 3; g++) {
                const float* pa = bA + 2 * s * PLANE + (mr + g) * MWP
                                  + colq + (lane & 3);
                unsigned a0 = __float_as_uint(pa[0]);
                unsigned a1 = __float_as_uint(pa[1]);
                unsigned a2 = __float_as_uint(pa[PLANE]);
                unsigned a3 = __float_as_uint(pa[PLANE + 1]);
                const float2* pb = bB + (s * 3 + g) * NT * 32 + lane;
#pragma unroll
                for (int nt = 0; nt < NT; nt++) {
                    float2 bb = pb[nt * 32];
                    mma_tf32(acc[nt], a0, a1, a2, a3,
                             __float_as_uint(bb.x), __float_as_uint(bb.y));
                }
            }
        }
        __syncthreads();
    }

    const int ho = h0 + mr;
#pragma unroll
    for (int nt = 0; nt < NT; nt++) {
        int n0 = nt * 8 + 2 * (lane & 3);
#pragma unroll
        for (int j = 0; j < 4; j++) {
            int n  = n0 + (j & 1);
            int wo = colq + (j >> 1);
            float v = acc[nt][j];
            v = v > 0.0f ? v : 0.0f;
            out[((size_t)(b * CO + n) * HW + ho) * HW + wo] = v;
        }
    }
}

// ---------------- conv + relu, f32x2 (c1) ----------------
template<int CI, int K, int CO, int COT, int WT,
         int HIN, int WIN, int HOUT, int WOUT, int ST, int PD, bool RND>
__global__ void conv_f2_k(const float* __restrict__ in, const float* __restrict__ wt,
                          const float* __restrict__ bias, float* __restrict__ out) {
    extern __shared__ float ws[];
    const int cob = blockIdx.y * COT;
    const int WROWS = CI * K * K;
    for (int i = threadIdx.x; i < WROWS * COT; i += 256) {
        int r = i / COT, c = i % COT;
        ws[i] = wt[r * CO + cob + c];
    }
    __syncthreads();

    const int warp = threadIdx.x >> 5, lane = threadIdx.x & 31;
    const int SPR = WOUT / (32 * WT);
    int seg = blockIdx.x * 8 + warp;
    int s   = seg % SPR;
    int row = seg / SPR;
    int h   = row % HOUT;
    int b   = row / HOUT;

    int wcol[WT];
#pragma unroll
    for (int k = 0; k < WT; k++) wcol[k] = s * 32 * WT + lane + 32 * k;

    unsigned long long acc[WT][COT / 2];
#pragma unroll
    for (int k = 0; k < WT; k++)
#pragma unroll
        for (int j = 0; j < COT / 2; j++)
            acc[k][j] = pk(bias[cob + 2 * j], bias[cob + 2 * j + 1]);

    const float* inb = in + (size_t)b * CI * HIN * WIN;
#pragma unroll 2
    for (int ci = 0; ci < CI; ci++) {
        const float* inp = inb + (size_t)ci * HIN * WIN;
#pragma unroll
        for (int kh = 0; kh < K; kh++) {
            int hi = h * ST - PD + kh;
            if ((unsigned)hi >= (unsigned)HIN) continue;
            const float* rp = inp + hi * WIN;
#pragma unroll
            for (int kw = 0; kw < K; kw++) {
                const ulonglong2* wv = reinterpret_cast<const ulonglong2*>(
                    ws + (ci * (K * K) + kh * K + kw) * COT);
                unsigned long long vv[WT];
#pragma unroll
                for (int k = 0; k < WT; k++) {
                    int wi = wcol[k] * ST - PD + kw;
                    float v = ((unsigned)wi < (unsigned)WIN) ? rp[wi] : 0.0f;
                    vv[k] = pk2(v);
                }
#pragma unroll
                for (int j = 0; j < COT / 4; j++) {
                    ulonglong2 w2 = wv[j];
#pragma unroll
                    for (int k = 0; k < WT; k++) {
                        fma2(acc[k][2 * j], vv[k], w2.x);
                        fma2(acc[k][2 * j + 1], vv[k], w2.y);
                    }
                }
            }
        }
    }

    size_t obase = ((size_t)b * CO + cob) * HOUT * WOUT + (size_t)h * WOUT;
#pragma unroll
    for (int k = 0; k < WT; k++)
#pragma unroll
        for (int j = 0; j < COT / 2; j++) {
            float2 r = up2(acc[k][j]);
            float v0 = r.x > 0.0f ? r.x : 0.0f;
            float v1 = r.y > 0.0f ? r.y : 0.0f;
            if (RND) { v0 = cvt_tf32(v0); v1 = cvt_tf32(v1); }
            out[obase + (size_t)(2 * j) * HOUT * WOUT + wcol[k]] = v0;
            out[obase + (size_t)(2 * j + 1) * HOUT * WOUT + wcol[k]] = v1;
        }
}

// ---------------- small-CO stride-1 conv + sigmoid (dc3), f32x2 spatial pairs ----------------
template<int CI, int K, int CO, int WT, int HIN, int WIN, int PD>
__global__ void conv_sig_k(const float* __restrict__ in, const float* __restrict__ wt,
                           const float* __restrict__ bias, float* __restrict__ out) {
    constexpr int HOUT = HIN, WOUT = WIN;
    extern __shared__ float ws[];
    for (int i = threadIdx.x; i < CI * K * K * CO; i += 256) ws[i] = wt[i];
    __syncthreads();

    const int warp = threadIdx.x >> 5, lane = threadIdx.x & 31;
    const int SPR = WOUT / (32 * WT);
    int seg = blockIdx.x * 8 + warp;
    int s   = seg % SPR;
    int row = seg / SPR;
    int h   = row % HOUT;
    int b   = row / HOUT;

    int wcol[WT];
#pragma unroll
    for (int k = 0; k < WT; k++) wcol[k] = s * 32 * WT + lane + 32 * k;

    unsigned long long acc[WT / 2][CO];
#pragma unroll
    for (int p = 0; p < WT / 2; p++)
#pragma unroll
        for (int c = 0; c < CO; c++) acc[p][c] = pk2(bias[c]);

    const float* inb = in + (size_t)b * CI * HIN * WIN;
#pragma unroll 2
    for (int ci = 0; ci < CI; ci++) {
        const float* inp = inb + (size_t)ci * HIN * WIN;
#pragma unroll
        for (int kh = 0; kh < K; kh++) {
            int hi = h - PD + kh;
            if ((unsigned)hi >= (unsigned)HIN) continue;
            const float* rp = inp + hi * WIN;
#pragma unroll
            for (int kw = 0; kw < K; kw++) {
                const float* wr = ws + (ci * (K * K) + kh * K + kw) * CO;
                float v[WT];
#pragma unroll
                for (int k = 0; k < WT; k++) {
                    int wi = wcol[k] - PD + kw;
                    v[k] = ((unsigned)wi < (unsigned)WIN) ? rp[wi] : 0.0f;
                }
#pragma unroll
                for (int c = 0; c < CO; c++) {
                    unsigned long long w2 = pk2(wr[c]);
#pragma unroll
                    for (int p = 0; p < WT / 2; p++)
                        fma2(acc[p][c], pk(v[2 * p], v[2 * p + 1]), w2);
                }
            }
        }
    }

    size_t obase = (size_t)b * CO * HOUT * WOUT + (size_t)h * WOUT;
#pragma unroll
    for (int p = 0; p < WT / 2; p++)
#pragma unroll
        for (int c = 0; c < CO; c++) {
            float2 r = up2(acc[p][c]);
            float v0 = 1.0f / (1.0f + __expf(-r.x));
            float v1 = 1.0f / (1.0f + __expf(-r.y));
            out[obase + (size_t)c * HOUT * WOUT + wcol[2 * p]] = v0;
            out[obase + (size_t)c * HOUT * WOUT + wcol[2 * p + 1]] = v1;
        }
}

// ---------------- vector quantize + q materialization (gather fused) ----------------
__global__ void vq_k(const float* __restrict__ emb, const float* __restrict__ z,
                     float* __restrict__ q) {
    extern __shared__ float sm[];
    float4* sp4 = (float4*)sm;               // 256*32 float4 paired codebook
    float2* sn2 = (float2*)(sm + 512 * 64);  // 256 norm pairs
    for (int i = threadIdx.x; i < 512 * 64; i += blockDim.x) {
        int k = i >> 6, j = i & 63;
        int dst = ((k >> 1) * 32 + (j >> 1)) * 4 + (j & 1) * 2 + (k & 1);
        sm[dst] = emb[i];
    }
    __syncthreads();
    for (int kp = threadIdx.x; kp < 256; kp += blockDim.x) {
        float sx = 0.0f, sy = 0.0f;
#pragma unroll
        for (int j2 = 0; j2 < 32; j2++) {
            float4 e = sp4[kp * 32 + j2];
            sx += e.x * e.x + e.z * e.z;
            sy += e.y * e.y + e.w * e.w;
        }
        sn2[kp] = make_float2(sx, sy);
    }
    __syncthreads();

    int n = blockIdx.x * blockDim.x + threadIdx.x;
    int b  = n >> 12;
    int hw = n & 4095;
    const float* zp = z + (size_t)b * 262144 + hw;
    float zr[64];
#pragma unroll
    for (int j = 0; j < 64; j++) zr[j] = zp[(size_t)j * 4096];

    float best = 3.4e38f;
    int bi = 0;
    for (int kp = 0; kp < 256; kp++) {
        const float4* ep = sp4 + kp * 32;
        unsigned long long dp = pk(0.0f, 0.0f);
#pragma unroll
        for (int j2 = 0; j2 < 32; j2++) {
            float4 e = ep[j2];
            fma2(dp, pk2(zr[2 * j2]),     pk(e.x, e.y));
            fma2(dp, pk2(zr[2 * j2 + 1]), pk(e.z, e.w));
        }
        float2 d2 = up2(dp);
        float2 nn = sn2[kp];
        float dx = nn.x - 2.0f * d2.x;
        if (dx < best) { best = dx; bi = 2 * kp; }
        float dy = nn.y - 2.0f * d2.y;
        if (dy < best) { best = dy; bi = 2 * kp + 1; }
    }

    float* qp = q + (size_t)b * 262144 + hw;
    float ls = 0.0f;
#pragma unroll
    for (int j = 0; j < 64; j++) {
        float e = sm[((bi >> 1) * 32 + (j >> 1)) * 4 + (j & 1) * 2 + (bi & 1)];
        qp[(size_t)j * 4096] = cvt_tf32(e);
        float df = e - zr[j];
        ls += df * df;
    }
#pragma unroll
    for (int o = 16; o > 0; o >>= 1) ls += __shfl_xor_sync(0xffffffffu, ls, o);
    if ((threadIdx.x & 31) == 0) atomicAdd(&g_loss, ls);
}

// ---------------- host ----------------
static float* sym_addr(const void* sym) {
    void* p = nullptr;
    cudaGetSymbolAddress(&p, sym);
    return (float*)p;
}

extern "C" void kernel_launch(void* const* d_in, const int* in_sizes, int n_in,
                              void* d_out, int out_size) {
    const float* x   = (const float*)d_in[0];
    const float* w1  = (const float*)d_in[1];
    const float* b1  = (const float*)d_in[2];
    const float* w2  = (const float*)d_in[3];
    const float* b2  = (const float*)d_in[4];
    const float* w3  = (const float*)d_in[5];
    const float* b3  = (const float*)d_in[6];
    const float* emb = (const float*)d_in[7];
    const float* dw1 = (const float*)d_in[8];
    const float* db1 = (const float*)d_in[9];
    const float* dw2 = (const float*)d_in[10];
    const float* db2 = (const float*)d_in[11];
    const float* dw3 = (const float*)d_in[12];
    const float* db3 = (const float*)d_in[13];
    float* out = (float*)d_out;

    float*  h1   = sym_addr(g_h1);
    float*  h2   = sym_addr(g_h2);
    float*  z    = sym_addr(g_z);
    float*  q    = sym_addr(g_q);
    float*  d1   = sym_addr(g_d1);
    float*  d2   = sym_addr(g_d2);
    float*  wt1  = sym_addr(g_wt1);
    float*  wt3d = sym_addr(g_wt3d);
    float2* pw1f = (float2*)sym_addr(g_pw1f);
    float2* pw2f = (float2*)sym_addr(g_pw2f);
    float2* cw2f = (float2*)sym_addr(g_cw2f);
    float2* cw3f = (float2*)sym_addr(g_cw3f);

    auto c1  = conv_f2_k<3, 4, 64, 32, 2, 256, 256, 128, 128, 2, 1, true>;
    auto c2m = conv2_mma_k<64, 128, 128, 128, 2, true>;     // KC 4->2 (residency 2->4 CTAs)
    auto c3m = conv3_mma_k<128, 64, 64, 4>;                 // KC 8->4 (residency 2->4 CTAs)
    auto dc1 = deconv_mma_k<64, 128, 2, 64, 80, 64, 64, 8, true>;
    auto dc2 = deconv_mma_k<128, 64, 1, 128, 144, 128, 128, 8, false>;
    auto dc3 = conv_sig_k<64, 3, 3, 4, 256, 256, 1>;

    // smem sizes
    const int smem_c2  = 2 * (2 * 6 * 130) * 4 + 2 * (2 * 2 * 16 * 32) * 8;  // 45248
    const int smem_c3  = 2 * (4 * 4 * 80) * 4 + 2 * (2 * 3 * 8 * 32) * 8;    // 34816
    const int smem_dc1 = 2 * (8 * 3 * 80) * 4 + 2 * (4 * 16 * 32) * 8;       // 48128
    const int smem_dc2 = 2 * (8 * 2 * 144) * 4 + 2 * (4 * 8 * 32) * 8;       // 34816
    const int smem_vq  = 512 * 64 * 4 + 256 * 8;                             // 133120

    cudaFuncSetAttribute(c2m, cudaFuncAttributeMaxDynamicSharedMemorySize, smem_c2);
    cudaFuncSetAttribute(c3m, cudaFuncAttributeMaxDynamicSharedMemorySize, smem_c3);
    cudaFuncSetAttribute(dc1, cudaFuncAttributeMaxDynamicSharedMemorySize, smem_dc1);
    cudaFuncSetAttribute(dc2, cudaFuncAttributeMaxDynamicSharedMemorySize, smem_dc2);
    cudaFuncSetAttribute(vq_k, cudaFuncAttributeMaxDynamicSharedMemorySize, smem_vq);

    // launch 1: fused repack (+ loss zero)
    repack_all_k<<<(217792 + 255) / 256, 256>>>(w1, w2, w3, dw1, dw2, dw3,
                                                wt1, cw2f, cw3f, pw1f, pw2f, wt3d);

    // launch 2-4: encoder  (c2m/c3m grids: tiles_h(32) * B(32) = 1024)
    c1<<<dim3(1024, 2), 256, 3 * 16 * 32 * 4>>>(x, wt1, b1, h1);
    c2m<<<dim3(32 * 32), 256, smem_c2>>>(h1, cw2f, b2, h2);
    c3m<<<dim3(32 * 32), 256, smem_c3>>>(h2, cw3f, b3, z);

    // launch 5: vector quantize (writes q directly)
    vq_k<<<512, 256, smem_vq>>>(emb, z, q);

    // launch 6-8: decoder (parity on blockIdx.x -> wave-adjacent, L2-hot input)
    dc1<<<dim3(4, 32 * 32), 256, smem_dc1>>>(q, pw1f, db1, d1);
    dc2<<<dim3(4, 128 * 32), 256, smem_dc2>>>(d1, pw2f, db2, d2);
    dc3<<<dim3(2048, 1), 256, 64 * 9 * 3 * 4>>>(d2, wt3d, db3, out);

    finalize_k<<<1, 1>>>(out, out_size - 1);
}